// round 16
// baseline (speedup 1.0000x reference)
#include <cuda_runtime.h>
#include <cuda_fp16.h>
#include <math.h>

// dims: B=2 N=2048 F=1024 H=16 D=64
#define OUTN 4194304ULL            /* start of kv region in d_out */
#define KV1  (OUTN + 4194304ULL)   /* start of kv[1] (v) */

// fp32 scratch
__device__ float g_Q[(size_t)32 * 2048 * 64];     // q (pre-scaled)

// packed fp16x2 planes (pairs along contraction / j dim)
__device__ unsigned g_sh[(size_t)32 * 2048 * 1024];   // scores fp16 pairs (256MB)
__device__ unsigned g_xh[4096 * 512],  g_xl[4096 * 512];
__device__ unsigned g_wqh[3072 * 512];
__device__ unsigned g_woh[1024 * 512];
__device__ unsigned g_qh[32 * 2048 * 32], g_ql[32 * 2048 * 32];
__device__ unsigned g_kh[32 * 2048 * 32];
__device__ unsigned g_vth[32 * 64 * 1024];
__device__ unsigned g_ph[(size_t)32 * 2048 * 1024];   // attn fp16 (single plane)
__device__ unsigned g_oh[4096 * 512], g_ol[4096 * 512];

// ---------------------------------------------------------------------------
__device__ __forceinline__ void split_pack(float x0, float x1,
                                           unsigned &hi, unsigned &lo)
{
    __half h0 = __float2half_rn(x0), h1 = __float2half_rn(x1);
    float f0 = __half2float(h0), f1 = __half2float(h1);
    __half l0 = __float2half_rn(x0 - f0), l1 = __float2half_rn(x1 - f1);
    hi = ((unsigned)__half_as_ushort(h1) << 16) | (unsigned)__half_as_ushort(h0);
    lo = ((unsigned)__half_as_ushort(l1) << 16) | (unsigned)__half_as_ushort(l0);
}
__device__ __forceinline__ unsigned pk_f16(float x0, float x1)
{
    __half h0 = __float2half_rn(x0), h1 = __float2half_rn(x1);
    return ((unsigned)__half_as_ushort(h1) << 16) | (unsigned)__half_as_ushort(h0);
}

__device__ __forceinline__ void mma_f16(float c[4],
                                        unsigned a0, unsigned a1, unsigned a2, unsigned a3,
                                        unsigned b0, unsigned b1)
{
    asm volatile(
        "mma.sync.aligned.m16n8k16.row.col.f32.f16.f16.f32 "
        "{%0,%1,%2,%3},{%4,%5,%6,%7},{%8,%9},{%0,%1,%2,%3};\n"
        : "+f"(c[0]), "+f"(c[1]), "+f"(c[2]), "+f"(c[3])
        : "r"(a0), "r"(a1), "r"(a2), "r"(a3), "r"(b0), "r"(b1));
}

__device__ __forceinline__ void ldmA(unsigned r[4], unsigned addr)
{
    asm volatile("ldmatrix.sync.aligned.m8n8.x4.shared.b16 {%0,%1,%2,%3}, [%4];"
                 : "=r"(r[0]), "=r"(r[1]), "=r"(r[2]), "=r"(r[3]) : "r"(addr));
}
__device__ __forceinline__ void ldmB(unsigned &r0, unsigned &r1, unsigned addr)
{
    asm volatile("ldmatrix.sync.aligned.m8n8.x2.shared.b16 {%0,%1}, [%2];"
                 : "=r"(r0), "=r"(r1) : "r"(addr));
}
__device__ __forceinline__ unsigned ldmA_addr(unsigned base, int ldu, int mr0, int kc, int lane)
{
    int row = mr0 + ((lane >> 3) & 1) * 8 + (lane & 7);
    int col = kc + ((lane >> 4) << 2);
    return base + (unsigned)(row * ldu + col) * 4u;
}
__device__ __forceinline__ unsigned ldmB_addr(unsigned base, int ldu, int nr0, int kc, int lane)
{
    int row = nr0 + (lane & 7);
    int col = kc + (((lane >> 3) & 1) << 2);
    return base + (unsigned)(row * ldu + col) * 4u;
}

__device__ __forceinline__ void cpa(unsigned dst, const unsigned* src)
{
    asm volatile("cp.async.cg.shared.global [%0], [%1], 16;" :: "r"(dst), "l"(src));
}
#define CP_COMMIT asm volatile("cp.async.commit_group;")
#define CP_WAIT0  asm volatile("cp.async.wait_group 0;")

// packed fp32x2 helpers
typedef unsigned long long ull;
__device__ __forceinline__ ull f2pk(float x, float y)
{ ull r; asm("mov.b64 %0,{%1,%2};" : "=l"(r) : "f"(x), "f"(y)); return r; }
__device__ __forceinline__ float2 f2up(ull r)
{ float2 v; asm("mov.b64 {%0,%1},%2;" : "=f"(v.x), "=f"(v.y) : "l"(r)); return v; }
__device__ __forceinline__ ull ffma2(ull a, ull b, ull c)
{ ull d; asm("fma.rn.f32x2 %0,%1,%2,%3;" : "=l"(d) : "l"(a), "l"(b), "l"(c)); return d; }

// ---------------------------------------------------------------------------
// pack input tensors: x split (2M pairs), wqkv single (1.5M), wout single (0.5M)
// ---------------------------------------------------------------------------
__global__ __launch_bounds__(256) void k_pack_in(const float* __restrict__ x,
                                                 const float* __restrict__ wq,
                                                 const float* __restrict__ wo)
{
    unsigned i = blockIdx.x * 256 + threadIdx.x;
    if (i < 2097152u) {
        float2 v = ((const float2*)x)[i];
        unsigned h, l;
        split_pack(v.x, v.y, h, l); g_xh[i] = h; g_xl[i] = l;
    } else if (i < 3670016u) {
        unsigned j = i - 2097152u;
        float2 v = ((const float2*)wq)[j];
        g_wqh[j] = pk_f16(v.x, v.y);
    } else if (i < 4194304u) {
        unsigned j = i - 3670016u;
        float2 v = ((const float2*)wo)[j];
        g_woh[j] = pk_f16(v.x, v.y);
    }
}

// ---------------------------------------------------------------------------
// pack q split (from g_Q), k single (kv0), v-transposed single (kv1)
// ---------------------------------------------------------------------------
__global__ __launch_bounds__(256) void k_pack_qkv(const float* __restrict__ out)
{
    unsigned i = blockIdx.x * 256 + threadIdx.x;   // 0 .. 6291455
    if (i < 2097152u) {
        float2 v = ((const float2*)g_Q)[i];
        unsigned h, l;
        split_pack(v.x, v.y, h, l); g_qh[i] = h; g_ql[i] = l;
    } else if (i < 4194304u) {
        unsigned j = i - 2097152u;
        float2 v = ((const float2*)(out + OUTN))[j];
        g_kh[j] = pk_f16(v.x, v.y);
    } else {
        unsigned j  = i - 4194304u;                // bh*65536 + d*1024 + jp
        unsigned bh = j >> 16, r = j & 65535u, d = r >> 10, jp = r & 1023u;
        const float* vb = out + KV1 + (size_t)bh * 131072;
        float v0 = vb[(size_t)(2 * jp) * 64 + d];
        float v1 = vb[(size_t)(2 * jp + 1) * 64 + d];
        g_vth[j] = pk_f16(v0, v1);
    }
}

// ---------------------------------------------------------------------------
// Kernel: QKV projection. M=4096, N=3072, Kdim=1024 (512 pairs).
// cp.async double-buffered; 2-term fp16 (x split, wqkv single). mma.sync.
// ---------------------------------------------------------------------------
__global__ __launch_bounds__(256, 2) void k_qkv(float* __restrict__ out)
{
    extern __shared__ unsigned sm[];
    const int t = threadIdx.x, warp = t >> 5, lane = t & 31;
    const int wm = warp >> 2, wn = warp & 3;
    const int g = lane >> 2, q = lane & 3;
    const int m0 = blockIdx.y * 128, n0 = blockIdx.x * 128;
    const unsigned smb = (unsigned)__cvta_generic_to_shared(sm);

    float acc[4][4][4];
#pragma unroll
    for (int i = 0; i < 4; i++)
#pragma unroll
        for (int j = 0; j < 4; j++)
#pragma unroll
            for (int c = 0; c < 4; c++) acc[i][j][c] = 0.f;

#define QKV_LOAD(s, ktp)                                                        \
    {                                                                           \
        unsigned base = smb + (s) * 30720;                                      \
        _Pragma("unroll")                                                       \
        for (int i = 0; i < 2; i++) {                                           \
            int c = t + i * 256; int row = c >> 2; int ch = (c & 3) * 4;        \
            unsigned off = (unsigned)(row * 20 + ch) * 4;                       \
            cpa(base + off,         g_xh  + (size_t)(m0 + row) * 512 + (ktp) + ch); \
            cpa(base + 10240 + off, g_xl  + (size_t)(m0 + row) * 512 + (ktp) + ch); \
            cpa(base + 20480 + off, g_wqh + (size_t)(n0 + row) * 512 + (ktp) + ch); \
        }                                                                       \
        CP_COMMIT;                                                              \
    }

    QKV_LOAD(0, 0);
    for (int it = 0; it < 32; it++) {
        CP_WAIT0; __syncthreads();
        if (it + 1 < 32) QKV_LOAD((it + 1) & 1, (it + 1) * 16);
        unsigned base = smb + (it & 1) * 30720;
#pragma unroll
        for (int ks = 0; ks < 2; ks++) {
            int kc = ks * 8;
            unsigned ah[4][4], al[4][4];
#pragma unroll
            for (int mi = 0; mi < 4; mi++) {
                ldmA(ah[mi], ldmA_addr(base,         20, wm * 64 + mi * 16, kc, lane));
                ldmA(al[mi], ldmA_addr(base + 10240, 20, wm * 64 + mi * 16, kc, lane));
            }
#pragma unroll
            for (int ni = 0; ni < 4; ni++) {
                unsigned bh0, bh1;
                ldmB(bh0, bh1, ldmB_addr(base + 20480, 20, wn * 32 + ni * 8, kc, lane));
#pragma unroll
                for (int mi = 0; mi < 4; mi++) {
                    mma_f16(acc[mi][ni], ah[mi][0], ah[mi][1], ah[mi][2], ah[mi][3], bh0, bh1);
                    mma_f16(acc[mi][ni], al[mi][0], al[mi][1], al[mi][2], al[mi][3], bh0, bh1);
                }
            }
        }
        __syncthreads();
    }

#pragma unroll
    for (int mi = 0; mi < 4; mi++) {
#pragma unroll
        for (int cc = 0; cc < 2; cc++) {
            int m  = m0 + wm * 64 + mi * 16 + g + cc * 8;
            int bb = m >> 11;
            int n  = m & 2047;
#pragma unroll
            for (int ni = 0; ni < 4; ni++) {
#pragma unroll
                for (int e = 0; e < 2; e++) {
                    int r = n0 + wn * 32 + ni * 8 + q * 2 + e;
                    float v = acc[mi][ni][cc * 2 + e];
                    int h = r / 192, rem = r - h * 192;
                    int d = rem / 3,  c = rem - d * 3;
                    if (c == 0) {
                        g_Q[(((size_t)(bb * 16 + h)) * 2048 + n) * 64 + d] = v * 0.125f;
                    } else {
                        out[OUTN + (((size_t)((c - 1) * 2 + bb) * 16 + h) * 2048 + n) * 64 + d] = v;
                    }
                }
            }
        }
    }
}

// ---------------------------------------------------------------------------
// Kernel: scores per (b,h). 2048x2048, Kdim=64. Writes packed fp16 S pairs.
// ---------------------------------------------------------------------------
__global__ __launch_bounds__(256, 2) void k_scores()
{
    extern __shared__ unsigned sm[];
    unsigned (*Qh)[36] = (unsigned(*)[36])(sm);
    unsigned (*Ql)[36] = (unsigned(*)[36])(sm + 4608);
    unsigned (*Kh)[36] = (unsigned(*)[36])(sm + 9216);

    const int t = threadIdx.x, warp = t >> 5, lane = t & 31;
    const int wm = warp >> 2, wn = warp & 3;
    const int g = lane >> 2, q = lane & 3;
    const int bh = blockIdx.z;
    const int m0 = blockIdx.y * 128, n0 = blockIdx.x * 128;
    const unsigned smb = (unsigned)__cvta_generic_to_shared(sm);

#pragma unroll
    for (int i = 0; i < 4; i++) {
        int c = t + i * 256;
        int row = c >> 3, ch = (c & 7) * 4;
        *(uint4*)&Qh[row][ch] = *(const uint4*)(g_qh + ((size_t)bh * 2048 + m0 + row) * 32 + ch);
        *(uint4*)&Ql[row][ch] = *(const uint4*)(g_ql + ((size_t)bh * 2048 + m0 + row) * 32 + ch);
        *(uint4*)&Kh[row][ch] = *(const uint4*)(g_kh + ((size_t)bh * 2048 + n0 + row) * 32 + ch);
    }
    __syncthreads();

    float acc[4][4][4];
#pragma unroll
    for (int i = 0; i < 4; i++)
#pragma unroll
        for (int j = 0; j < 4; j++)
#pragma unroll
            for (int c = 0; c < 4; c++) acc[i][j][c] = 0.f;

#pragma unroll
    for (int ks = 0; ks < 4; ks++) {
        int kc = ks * 8;
        unsigned ah[4][4], al[4][4];
#pragma unroll
        for (int mi = 0; mi < 4; mi++) {
            ldmA(ah[mi], ldmA_addr(smb,         36, wm * 64 + mi * 16, kc, lane));
            ldmA(al[mi], ldmA_addr(smb + 18432, 36, wm * 64 + mi * 16, kc, lane));
        }
#pragma unroll
        for (int ni = 0; ni < 4; ni++) {
            unsigned bh0, bh1;
            ldmB(bh0, bh1, ldmB_addr(smb + 36864, 36, wn * 32 + ni * 8, kc, lane));
#pragma unroll
            for (int mi = 0; mi < 4; mi++) {
                mma_f16(acc[mi][ni], ah[mi][0], ah[mi][1], ah[mi][2], ah[mi][3], bh0, bh1);
                mma_f16(acc[mi][ni], al[mi][0], al[mi][1], al[mi][2], al[mi][3], bh0, bh1);
            }
        }
    }

#pragma unroll
    for (int mi = 0; mi < 4; mi++) {
#pragma unroll
        for (int cc = 0; cc < 2; cc++) {
            int m = m0 + wm * 64 + mi * 16 + g + cc * 8;
            unsigned* Sp = g_sh + ((size_t)bh * 2048 + m) * 1024;
#pragma unroll
            for (int ni = 0; ni < 4; ni++) {
                int np = (n0 + wn * 32 + ni * 8) / 2 + q;   // pair index
                __stcs(Sp + np, pk_f16(acc[mi][ni][cc * 2], acc[mi][ni][cc * 2 + 1]));
            }
        }
    }
}

// ---------------------------------------------------------------------------
// Kernel: fused premix + softmax + postmix. One CTA per (b, i).
// Head-mixes run on the TENSOR pipe: 16x16 W as mma A-fragments (2-term fp16
// split, computed per-lane from the documented m16n8k16 layout); S columns
// gathered as B-fragments. Premix B-conversion is lossless (S is exact fp16).
// Each warp owns an exclusive 8-column window per mma -> no in-place hazard.
// ---------------------------------------------------------------------------
__global__ __launch_bounds__(1024) void k_mix(const float* __restrict__ wpre,
                                              const float* __restrict__ bpre,
                                              const float* __restrict__ wpost,
                                              const float* __restrict__ bpost)
{
    extern __shared__ float S[];             // 16 x 2048 fp32

    const int t  = threadIdx.x;
    const int warp = t >> 5, lane = t & 31;
    const int bi = blockIdx.x;
    const int b  = bi >> 11;
    const int i  = bi & 2047;

    // per-lane W fragments (a0..a3 of m16n8k16 row-major A), 2-term split
    const int am = lane >> 2;          // m rows am, am+8
    const int ak = (lane & 3) * 2;     // k cols ak,ak+1 (+8 for a2/a3)
    unsigned pah[4], pal[4], qah[4], qal[4];
    split_pack(wpre[am * 16 + ak],        wpre[am * 16 + ak + 1],        pah[0], pal[0]);
    split_pack(wpre[(am + 8) * 16 + ak],  wpre[(am + 8) * 16 + ak + 1],  pah[1], pal[1]);
    split_pack(wpre[am * 16 + ak + 8],    wpre[am * 16 + ak + 9],        pah[2], pal[2]);
    split_pack(wpre[(am + 8) * 16 + ak + 8], wpre[(am + 8) * 16 + ak + 9], pah[3], pal[3]);
    split_pack(wpost[am * 16 + ak],        wpost[am * 16 + ak + 1],        qah[0], qal[0]);
    split_pack(wpost[(am + 8) * 16 + ak],  wpost[(am + 8) * 16 + ak + 1],  qah[1], qal[1]);
    split_pack(wpost[am * 16 + ak + 8],    wpost[am * 16 + ak + 9],        qah[2], qal[2]);
    split_pack(wpost[(am + 8) * 16 + ak + 8], wpost[(am + 8) * 16 + ak + 9], qah[3], qal[3]);
    const float bp0 = bpre[am],  bp1 = bpre[am + 8];
    const float bq0 = bpost[am], bq1 = bpost[am + 8];

    // load 16 head rows (fp16 pairs -> fp32): 16 x 256 uint4, 1024 threads x 4
#pragma unroll
    for (int it = 0; it < 4; it++) {
        int idx = t + it * 1024;
        int h   = idx >> 8;
        int u4  = idx & 255;
        uint4 u = __ldcs((const uint4*)(g_sh + (((size_t)(b * 16 + h)) * 2048 + i) * 1024) + u4);
        float2 fa = __half22float2(*(__half2*)&u.x);
        float2 fb = __half22float2(*(__half2*)&u.y);
        float2 fc = __half22float2(*(__half2*)&u.z);
        float2 fd = __half22float2(*(__half2*)&u.w);
        float* dst = S + h * 2048 + u4 * 8;
        *(float4*)dst       = make_float4(fa.x, fa.y, fb.x, fb.y);
        *(float4*)(dst + 4) = make_float4(fc.x, fc.y, fd.x, fd.y);
    }
    __syncthreads();

    // premix via mma: warp owns columns [warp*64, warp*64+64)
    const int kb = ak;                 // B frag k rows kb,kb+1 (+8 for b1)
#pragma unroll
    for (int it2 = 0; it2 < 8; it2++) {
        int jb = warp * 64 + it2 * 8;
        int jB = jb + (lane >> 2);
        unsigned b0 = pk_f16(S[kb * 2048 + jB],       S[(kb + 1) * 2048 + jB]);
        unsigned b1 = pk_f16(S[(kb + 8) * 2048 + jB], S[(kb + 9) * 2048 + jB]);
        float c[4] = {bp0, bp0, bp1, bp1};
        mma_f16(c, pah[0], pah[1], pah[2], pah[3], b0, b1);
        mma_f16(c, pal[0], pal[1], pal[2], pal[3], b0, b1);
        int jc = jb + (lane & 3) * 2;
        *(float2*)&S[am * 2048 + jc]       = make_float2(c[0], c[1]);
        *(float2*)&S[(am + 8) * 2048 + jc] = make_float2(c[2], c[3]);
    }
    __syncthreads();

    // softmax: warps 0..15 each own one head row
    if (warp < 16) {
        float* row = S + warp * 2048;
        float m = -1e30f;
        for (int j = lane; j < 2048; j += 32) m = fmaxf(m, row[j]);
#pragma unroll
        for (int o = 16; o; o >>= 1) m = fmaxf(m, __shfl_xor_sync(0xffffffffu, m, o));
        float z = 0.f;
        for (int j = lane; j < 2048; j += 32) {
            float e = __expf(row[j] - m);
            row[j] = e;
            z += e;
        }
#pragma unroll
        for (int o = 16; o; o >>= 1) z += __shfl_xor_sync(0xffffffffu, z, o);
        float inv = 1.f / z;
        for (int j = lane; j < 2048; j += 32) row[j] *= inv;
    }
    __syncthreads();

    // postmix via mma -> fp16 plane in global
#pragma unroll
    for (int it2 = 0; it2 < 8; it2++) {
        int jb = warp * 64 + it2 * 8;
        int jB = jb + (lane >> 2);
        unsigned b0 = pk_f16(S[kb * 2048 + jB],       S[(kb + 1) * 2048 + jB]);
        unsigned b1 = pk_f16(S[(kb + 8) * 2048 + jB], S[(kb + 9) * 2048 + jB]);
        float c[4] = {bq0, bq0, bq1, bq1};
        mma_f16(c, qah[0], qah[1], qah[2], qah[3], b0, b1);
        mma_f16(c, qal[0], qal[1], qal[2], qal[3], b0, b1);
        int jp = (jb >> 1) + (lane & 3);
        g_ph[(((size_t)(b * 16 + am))     * 2048 + i) * 1024 + jp] = pk_f16(c[0], c[1]);
        g_ph[(((size_t)(b * 16 + am + 8)) * 2048 + i) * 1024 + jp] = pk_f16(c[2], c[3]);
    }
}

// ---------------------------------------------------------------------------
// Kernel: AV per (b,h). O = P @ V; single-plane P, single-plane V.
// ---------------------------------------------------------------------------
__global__ __launch_bounds__(256, 2) void k_av()
{
    extern __shared__ unsigned sm[];
    const int t = threadIdx.x, warp = t >> 5, lane = t & 31;
    const int wm = warp >> 2, wn = warp & 3;
    const int g = lane >> 2, q = lane & 3;
    const int bh = blockIdx.z;
    const int m0 = blockIdx.y * 128;
    const unsigned smb = (unsigned)__cvta_generic_to_shared(sm);

    float acc[4][2][4];
#pragma unroll
    for (int i = 0; i < 4; i++)
#pragma unroll
        for (int j = 0; j < 2; j++)
#pragma unroll
            for (int c = 0; c < 4; c++) acc[i][j][c] = 0.f;

    const size_t pbase = (size_t)bh * 2048 * 1024;
    const size_t vbase = (size_t)bh * 64 * 1024;

#define AV_LOAD(s, ktp)                                                         \
    {                                                                           \
        unsigned base = smb + (s) * 15360;                                      \
        _Pragma("unroll")                                                       \
        for (int i = 0; i < 2; i++) {                                           \
            int c = t + i * 256; int row = c >> 2; int ch = (c & 3) * 4;        \
            unsigned off = (unsigned)(row * 20 + ch) * 4;                       \
            cpa(base + off, g_ph + pbase + (size_t)(m0 + row) * 1024 + (ktp) + ch); \
        }                                                                       \
        {                                                                       \
            int c = t; int row = c >> 2; int ch = (c & 3) * 4;                  \
            unsigned off = (unsigned)(row * 20 + ch) * 4;                       \
            cpa(base + 10240 + off, g_vth + vbase + (size_t)row * 1024 + (ktp) + ch); \
        }                                                                       \
        CP_COMMIT;                                                              \
    }

    AV_LOAD(0, 0);
    for (int it = 0; it < 64; it++) {
        CP_WAIT0; __syncthreads();
        if (it + 1 < 64) AV_LOAD((it + 1) & 1, (it + 1) * 16);
        unsigned base = smb + (it & 1) * 15360;
#pragma unroll
        for (int ks = 0; ks < 2; ks++) {
            int kc = ks * 8;
            unsigned ah[4][4];
#pragma unroll
            for (int mi = 0; mi < 4; mi++)
                ldmA(ah[mi], ldmA_addr(base, 20, wm * 64 + mi * 16, kc, lane));
#pragma unroll
            for (int ni = 0; ni < 2; ni++) {
                unsigned bh0, bh1;
                ldmB(bh0, bh1, ldmB_addr(base + 10240, 20, wn * 16 + ni * 8, kc, lane));
#pragma unroll
                for (int mi = 0; mi < 4; mi++)
                    mma_f16(acc[mi][ni], ah[mi][0], ah[mi][1], ah[mi][2], ah[mi][3], bh0, bh1);
            }
        }
        __syncthreads();
    }

    const int b = bh >> 4, h = bh & 15;
#pragma unroll
    for (int mi = 0; mi < 4; mi++) {
#pragma unroll
        for (int ni = 0; ni < 2; ni++) {
            int m  = m0 + wm * 64 + mi * 16 + g;
            int dp = h * 32 + wn * 8 + ni * 4 + q;
            unsigned hh, ll;
            split_pack(acc[mi][ni][0], acc[mi][ni][1], hh, ll);
            size_t idx = ((size_t)(b * 2048 + m)) * 512 + dp;
            g_oh[idx] = hh; g_ol[idx] = ll;
            split_pack(acc[mi][ni][2], acc[mi][ni][3], hh, ll);
            idx = ((size_t)(b * 2048 + m + 8)) * 512 + dp;
            g_oh[idx] = hh; g_ol[idx] = ll;
        }
    }
}

// ---------------------------------------------------------------------------
// Kernel: out projection. M=4096, N=1024, Kdim=1024 (512 pairs), 2-term fp16.
// ---------------------------------------------------------------------------
__global__ __launch_bounds__(256, 2) void k_out(float* __restrict__ out)
{
    extern __shared__ unsigned sm[];
    const int t = threadIdx.x, warp = t >> 5, lane = t & 31;
    const int wm = warp >> 2, wn = warp & 3;
    const int g = lane >> 2, q = lane & 3;
    const int m0 = blockIdx.y * 128, n0 = blockIdx.x * 128;
    const unsigned smb = (unsigned)__cvta_generic_to_shared(sm);

    float acc[4][4][4];
#pragma unroll
    for (int i = 0; i < 4; i++)
#pragma unroll
        for (int j = 0; j < 4; j++)
#pragma unroll
            for (int c = 0; c < 4; c++) acc[i][j][c] = 0.f;

#define OUT_LOAD(s, ktp)                                                        \
    {                                                                           \
        unsigned base = smb + (s) * 30720;                                      \
        _Pragma("unroll")                                                       \
        for (int i = 0; i < 2; i++) {                                           \
            int c = t + i * 256; int row = c >> 2; int ch = (c & 3) * 4;        \
            unsigned off = (unsigned)(row * 20 + ch) * 4;                       \
            cpa(base + off,         g_oh  + (size_t)(m0 + row) * 512 + (ktp) + ch); \
            cpa(base + 10240 + off, g_ol  + (size_t)(m0 + row) * 512 + (ktp) + ch); \
            cpa(base + 20480 + off, g_woh + (size_t)(n0 + row) * 512 + (ktp) + ch); \
        }                                                                       \
        CP_COMMIT;                                                              \
    }

    OUT_LOAD(0, 0);
    for (int it = 0; it < 32; it++) {
        CP_WAIT0; __syncthreads();
        if (it + 1 < 32) OUT_LOAD((it + 1) & 1, (it + 1) * 16);
        unsigned base = smb + (it & 1) * 30720;
#pragma unroll
        for (int ks = 0; ks < 2; ks++) {
            int kc = ks * 8;
            unsigned ah[4][4], al[4][4];
#pragma unroll
            for (int mi = 0; mi < 4; mi++) {
                ldmA(ah[mi], ldmA_addr(base,         20, wm * 64 + mi * 16, kc, lane));
                ldmA(al[mi], ldmA_addr(base + 10240, 20, wm * 64 + mi * 16, kc, lane));
            }
#pragma unroll
            for (int ni = 0; ni < 4; ni++) {
                unsigned bh0, bh1;
                ldmB(bh0, bh1, ldmB_addr(base + 20480, 20, wn * 32 + ni * 8, kc, lane));
#pragma unroll
                for (int mi = 0; mi < 4; mi++) {
                    mma_f16(acc[mi][ni], ah[mi][0], ah[mi][1], ah[mi][2], ah[mi][3], bh0, bh1);
                    mma_f16(acc[mi][ni], al[mi][0], al[mi][1], al[mi][2], al[mi][3], bh0, bh1);
                }
            }
        }
        __syncthreads();
    }

#pragma unroll
    for (int mi = 0; mi < 4; mi++) {
#pragma unroll
        for (int cc = 0; cc < 2; cc++) {
            int m = m0 + wm * 64 + mi * 16 + g + cc * 8;
            float* Op = out + (size_t)m * 1024;
#pragma unroll
            for (int ni = 0; ni < 4; ni++) {
                int n = n0 + wn * 32 + ni * 8 + q * 2;
                *(float2*)(Op + n) = make_float2(acc[mi][ni][cc * 2],
                                                 acc[mi][ni][cc * 2 + 1]);
            }
        }
    }
}

// ---------------------------------------------------------------------------
extern "C" void kernel_launch(void* const* d_in, const int* in_sizes, int n_in,
                              void* d_out, int out_size)
{
    const float* x     = (const float*)d_in[0];
    const float* wqkv  = (const float*)d_in[1];
    const float* wout  = (const float*)d_in[2];
    const float* wpre  = (const float*)d_in[3];
    const float* bpre  = (const float*)d_in[4];
    const float* wpost = (const float*)d_in[5];
    const float* bpost = (const float*)d_in[6];
    float* out = (float*)d_out;

    const int SMIX = 16 * 2048 * 4;    // 131,072 B

    cudaFuncSetAttribute(k_qkv,    cudaFuncAttributeMaxDynamicSharedMemorySize, 61440);
    cudaFuncSetAttribute(k_scores, cudaFuncAttributeMaxDynamicSharedMemorySize, 55296);
    cudaFuncSetAttribute(k_mix,    cudaFuncAttributeMaxDynamicSharedMemorySize, SMIX);
    cudaFuncSetAttribute(k_av,     cudaFuncAttributeMaxDynamicSharedMemorySize, 30720);
    cudaFuncSetAttribute(k_out,    cudaFuncAttributeMaxDynamicSharedMemorySize, 61440);

    k_pack_in<<<16384, 256>>>(x, wqkv, wout);
    k_qkv<<<dim3(24, 32), 256, 61440>>>(out);
    k_pack_qkv<<<24576, 256>>>(out);
    k_scores<<<dim3(16, 16, 32), 256, 55296>>>();
    k_mix<<<4096, 1024, SMIX>>>(wpre, bpre, wpost, bpost);
    k_av<<<dim3(1, 16, 32), 256, 30720>>>();
    k_out<<<dim3(8, 32), 256, 61440>>>(out);
}